// round 16
// baseline (speedup 1.0000x reference)
#include <cuda_runtime.h>
#include <cstdint>

#define NMAX 10000
#define EMAX 100000
#define FDIM 128
#define KDIM 16
#define RDIM 8
#define HDIM 64

// ---------------- scratch (static __device__ arrays; no allocation) ----------------
__device__ float g_x[NMAX * FDIM];                 // node_feats @ W_up        (5.1 MB)
__device__ float g_ew[EMAX * KDIM];                // masked weighted edge attrs (6.4 MB)
__device__ float g_agg[(size_t)NMAX * KDIM * FDIM];// aggregated messages, [n][f*16+k] (82 MB)
__device__ float g_wdp[KDIM * FDIM * FDIM];        // permuted W_down (1 MB)
__device__ float g_part[2][NMAX * FDIM];           // split-K partial sums (10.2 MB)
__device__ int   g_counts[NMAX];
__device__ int   g_offsets[NMAX + 1];
__device__ int   g_cursor[NMAX];
__device__ int   g_sorted[EMAX];

typedef unsigned long long ull;

// ---------------- f32x2 packed-FMA helpers (sm_103a) ----------------
__device__ __forceinline__ ull pack2(float x, float y) {
    ull r; asm("mov.b64 %0, {%1, %2};" : "=l"(r) : "f"(x), "f"(y)); return r;
}
__device__ __forceinline__ void unpack2(ull v, float& x, float& y) {
    asm("mov.b64 {%0, %1}, %2;" : "=f"(x), "=f"(y) : "l"(v));
}
__device__ __forceinline__ ull ffma2(ull a, ull b, ull c) {
    ull d; asm("fma.rn.f32x2 %0, %1, %2, %3;" : "=l"(d) : "l"(a), "l"(b), "l"(c)); return d;
}

// =====================================================================
// Split-K fp32 GEMM:  Cpart[split][M,128] = A[M, kbase:kbase+K/2] @ B[., 128]
// BM=128, BN=128, BK=16, 256 threads, gridDim.y = 2 splits.
// Microtile 8 rows x 8 cols (4 FFMA2 col-pairs). Double-buffered smem,
// single __syncthreads per k-tile.
// Thread (rt = tid>>4, ct = tid&15): rows rt*8..+7, col pairs {2ct,2ct+1}+32j.
// A reads: warp-broadcast (rt uniform in half-warp groups) - conflict-free.
// B reads: 16 consecutive ull per j - conflict-free.
// =====================================================================
__global__ void k_gemm(const float* __restrict__ A,
                       const float* __restrict__ B,
                       int M, int K)
{
    __shared__ ull As2[2][16][128];  // (a,a) duplicated pairs, 32 KB
    __shared__ ull Bs [2][16][64];   // column pairs,            16 KB

    const int tid = threadIdx.x;
    const int rt  = tid >> 4;              // 0..15 row tile
    const int ct  = tid & 15;              // 0..15 col tile
    const int m0  = blockIdx.x * 128;
    const int Ksplit = K >> 1;
    const int kbase  = blockIdx.y * Ksplit;
    float* __restrict__ Cp = &g_part[blockIdx.y][0];

    const int ntiles = Ksplit >> 4;

    // fill mappings (2 float4 per thread for each of A and B)
    const int qa0 = tid, qa1 = tid + 256;          // A float4 ids 0..511
    const int ar0 = qa0 >> 2, ak0 = (qa0 & 3) << 2;
    const int ar1 = qa1 >> 2, ak1 = (qa1 & 3) << 2;
    const int br0 = qa0 >> 5, bc0 = (qa0 & 31) << 2;
    const int br1 = qa1 >> 5, bc1 = (qa1 & 31) << 2;

    ull acc[8][4];
#pragma unroll
    for (int i = 0; i < 8; i++)
#pragma unroll
        for (int j = 0; j < 4; j++) acc[i][j] = 0ull;

    float4 pa0, pa1, pb0, pb1;

    // prefetch tile 0
    {
        const int kb = kbase;
        pa0 = (m0 + ar0 < M) ? *(const float4*)(A + (size_t)(m0 + ar0) * K + kb + ak0)
                             : make_float4(0.f, 0.f, 0.f, 0.f);
        pa1 = (m0 + ar1 < M) ? *(const float4*)(A + (size_t)(m0 + ar1) * K + kb + ak1)
                             : make_float4(0.f, 0.f, 0.f, 0.f);
        pb0 = *(const float4*)(B + (size_t)(kb + br0) * 128 + bc0);
        pb1 = *(const float4*)(B + (size_t)(kb + br1) * 128 + bc1);
    }
    // store tile 0 into buffer 0
    {
        As2[0][ak0 + 0][ar0] = pack2(pa0.x, pa0.x);
        As2[0][ak0 + 1][ar0] = pack2(pa0.y, pa0.y);
        As2[0][ak0 + 2][ar0] = pack2(pa0.z, pa0.z);
        As2[0][ak0 + 3][ar0] = pack2(pa0.w, pa0.w);
        As2[0][ak1 + 0][ar1] = pack2(pa1.x, pa1.x);
        As2[0][ak1 + 1][ar1] = pack2(pa1.y, pa1.y);
        As2[0][ak1 + 2][ar1] = pack2(pa1.z, pa1.z);
        As2[0][ak1 + 3][ar1] = pack2(pa1.w, pa1.w);
        const int c20 = bc0 >> 1, c21 = bc1 >> 1;
        Bs[0][br0][c20]     = pack2(pb0.x, pb0.y);
        Bs[0][br0][c20 + 1] = pack2(pb0.z, pb0.w);
        Bs[0][br1][c21]     = pack2(pb1.x, pb1.y);
        Bs[0][br1][c21 + 1] = pack2(pb1.z, pb1.w);
    }
    __syncthreads();

    const int rbase = rt * 8;

    for (int kt = 0; kt < ntiles; ++kt) {
        const int cur = kt & 1;
        const bool more = (kt + 1 < ntiles);

        if (more) {   // issue global prefetch early
            const int kb = kbase + (kt + 1) * 16;
            pa0 = (m0 + ar0 < M) ? *(const float4*)(A + (size_t)(m0 + ar0) * K + kb + ak0)
                                 : make_float4(0.f, 0.f, 0.f, 0.f);
            pa1 = (m0 + ar1 < M) ? *(const float4*)(A + (size_t)(m0 + ar1) * K + kb + ak1)
                                 : make_float4(0.f, 0.f, 0.f, 0.f);
            pb0 = *(const float4*)(B + (size_t)(kb + br0) * 128 + bc0);
            pb1 = *(const float4*)(B + (size_t)(kb + br1) * 128 + bc1);
        }

#pragma unroll
        for (int k = 0; k < 16; ++k) {
            ull a[8], b[4];
#pragma unroll
            for (int i = 0; i < 8; i++) a[i] = As2[cur][k][rbase + i];
#pragma unroll
            for (int j = 0; j < 4; j++) b[j] = Bs[cur][k][ct + 16 * j];
#pragma unroll
            for (int i = 0; i < 8; i++) {
#pragma unroll
                for (int j = 0; j < 4; j++)
                    acc[i][j] = ffma2(a[i], b[j], acc[i][j]);
            }
        }

        if (more) {
            const int nxt = cur ^ 1;
            As2[nxt][ak0 + 0][ar0] = pack2(pa0.x, pa0.x);
            As2[nxt][ak0 + 1][ar0] = pack2(pa0.y, pa0.y);
            As2[nxt][ak0 + 2][ar0] = pack2(pa0.z, pa0.z);
            As2[nxt][ak0 + 3][ar0] = pack2(pa0.w, pa0.w);
            As2[nxt][ak1 + 0][ar1] = pack2(pa1.x, pa1.x);
            As2[nxt][ak1 + 1][ar1] = pack2(pa1.y, pa1.y);
            As2[nxt][ak1 + 2][ar1] = pack2(pa1.z, pa1.z);
            As2[nxt][ak1 + 3][ar1] = pack2(pa1.w, pa1.w);
            const int c20 = bc0 >> 1, c21 = bc1 >> 1;
            Bs[nxt][br0][c20]     = pack2(pb0.x, pb0.y);
            Bs[nxt][br0][c20 + 1] = pack2(pb0.z, pb0.w);
            Bs[nxt][br1][c21]     = pack2(pb1.x, pb1.y);
            Bs[nxt][br1][c21 + 1] = pack2(pb1.z, pb1.w);
            __syncthreads();
        }
    }

#pragma unroll
    for (int i = 0; i < 8; i++) {
        const int row = m0 + rbase + i;
        if (row < M) {
#pragma unroll
            for (int j = 0; j < 4; j++) {
                float lo, hi; unpack2(acc[i][j], lo, hi);
                *(float2*)(Cp + (size_t)row * 128 + 2 * ct + 32 * j) =
                    make_float2(lo, hi);
            }
        }
    }
}

// combine split-K partials: dst = scale * (p0 + p1), float4 vectorized
__global__ void k_combine(float* __restrict__ dst, float scale, int n4) {
    const int i = blockIdx.x * 256 + threadIdx.x;
    if (i >= n4) return;
    const float4 a = ((const float4*)&g_part[0][0])[i];
    const float4 b = ((const float4*)&g_part[1][0])[i];
    ((float4*)dst)[i] = make_float4(scale * (a.x + b.x), scale * (a.y + b.y),
                                    scale * (a.z + b.z), scale * (a.w + b.w));
}

// ---------------- W_down permutation: row k*128+f  ->  row f*16+k ----------------
__global__ void k_permute(const float* __restrict__ Wd) {
    const int idx = blockIdx.x * 256 + threadIdx.x;
    if (idx >= KDIM * FDIM * FDIM) return;
    const int col = idx & 127;
    const int row = idx >> 7;       // 0..2047 = k*128+f
    const int k   = row >> 7;
    const int f   = row & 127;
    g_wdp[((f << 4) + k) * 128 + col] = Wd[idx];
}

// ---------------- radial MLP + masked edge weighting -> g_ew ----------------
// edge_mask arrives as int32 (harness promotes bool -> int32).
__global__ void k_radial(const float* __restrict__ radial,
                         const float* __restrict__ ef,
                         const int* __restrict__ mask,
                         const float* __restrict__ W1,
                         const float* __restrict__ W2,
                         int E)
{
    __shared__ float W1t[HDIM * RDIM];        // transposed: [j][i], 2 KB
    __shared__ ull   W2p[HDIM * KDIM / 2];    // row pairs:  [j][kp], 4 KB
    const int tid = threadIdx.x;
    for (int idx = tid; idx < HDIM * RDIM; idx += 256) {
        const int j = idx >> 3, i = idx & 7;
        W1t[idx] = W1[i * HDIM + j];
    }
    for (int idx = tid; idx < HDIM * KDIM / 2; idx += 256)
        W2p[idx] = pack2(W2[2 * idx], W2[2 * idx + 1]);
    __syncthreads();

    const int e = blockIdx.x * 256 + tid;
    if (e >= E) return;

    const float4 r0 = *(const float4*)(radial + (size_t)e * 8);
    const float4 r1 = *(const float4*)(radial + (size_t)e * 8 + 4);

    ull w[8];
#pragma unroll
    for (int kp = 0; kp < 8; kp++) w[kp] = 0ull;

#pragma unroll 4
    for (int j = 0; j < HDIM; j++) {
        const float4 c0 = *(const float4*)&W1t[j * 8];
        const float4 c1 = *(const float4*)&W1t[j * 8 + 4];
        float h = r0.x * c0.x;
        h = fmaf(r0.y, c0.y, h); h = fmaf(r0.z, c0.z, h); h = fmaf(r0.w, c0.w, h);
        h = fmaf(r1.x, c1.x, h); h = fmaf(r1.y, c1.y, h);
        h = fmaf(r1.z, c1.z, h); h = fmaf(r1.w, c1.w, h);
        const float s = __fdividef(h, 1.0f + __expf(-h));   // silu
        const ull ss = pack2(s, s);
        const ulonglong2* wp = (const ulonglong2*)&W2p[j * 8];
#pragma unroll
        for (int q = 0; q < 4; q++) {
            const ulonglong2 t = wp[q];
            w[2 * q]     = ffma2(ss, t.x, w[2 * q]);
            w[2 * q + 1] = ffma2(ss, t.y, w[2 * q + 1]);
        }
    }

    float wk[16];
#pragma unroll
    for (int kp = 0; kp < 8; kp++) unpack2(w[kp], wk[2 * kp], wk[2 * kp + 1]);

    const float m = (mask[e] != 0) ? 1.0f : 0.0f;
    const float4* efp = (const float4*)(ef + (size_t)e * 16);
    float4* op = (float4*)(g_ew + (size_t)e * 16);
#pragma unroll
    for (int q = 0; q < 4; q++) {
        const float4 v = efp[q];
        op[q] = make_float4(m * v.x * wk[q * 4 + 0], m * v.y * wk[q * 4 + 1],
                            m * v.z * wk[q * 4 + 2], m * v.w * wk[q * 4 + 3]);
    }
}

// ---------------- counting sort of edges by receiver ----------------
__global__ void k_zero_counts(int n) {
    const int i = blockIdx.x * 256 + threadIdx.x;
    if (i < n) g_counts[i] = 0;
}
__global__ void k_hist(const int* __restrict__ recv, int E) {
    const int e = blockIdx.x * 256 + threadIdx.x;
    if (e < E) atomicAdd(&g_counts[recv[e]], 1);
}
__global__ void k_scan(int n) {
    __shared__ int wsum[32];
    const int tid  = threadIdx.x;
    const int lane = tid & 31;
    const int wid  = tid >> 5;
    int carry = 0;
    for (int base = 0; base < n; base += 1024) {
        const int i = base + tid;
        const int v = (i < n) ? g_counts[i] : 0;
        int x = v;
#pragma unroll
        for (int off = 1; off < 32; off <<= 1) {
            const int y = __shfl_up_sync(0xffffffffu, x, off);
            if (lane >= off) x += y;
        }
        if (lane == 31) wsum[wid] = x;
        __syncthreads();
        if (wid == 0) {
            int s = wsum[lane];
#pragma unroll
            for (int off = 1; off < 32; off <<= 1) {
                const int y = __shfl_up_sync(0xffffffffu, s, off);
                if (lane >= off) s += y;
            }
            wsum[lane] = s;
        }
        __syncthreads();
        const int wbase = (wid > 0) ? wsum[wid - 1] : 0;
        const int excl  = carry + wbase + x - v;
        if (i < n) { g_offsets[i] = excl; g_cursor[i] = excl; }
        carry += wsum[31];
        __syncthreads();
    }
    if (tid == 0) g_offsets[n] = carry;
}
__global__ void k_scatter(const int* __restrict__ recv, int E) {
    const int e = blockIdx.x * 256 + threadIdx.x;
    if (e < E) {
        const int p = atomicAdd(&g_cursor[recv[e]], 1);
        g_sorted[p] = e;
    }
}

// ---------------- per-receiver aggregation -> g_agg [n][f*16+k] ----------------
__global__ void k_agg(const int* __restrict__ senders) {
    const int n = blockIdx.x;
    const int f = threadIdx.x;     // 128 threads, one output channel each
    const int s0 = g_offsets[n];
    const int s1 = g_offsets[n + 1];
    float acc[16];
#pragma unroll
    for (int k = 0; k < 16; k++) acc[k] = 0.f;

    for (int i = s0; i < s1; ++i) {
        const int e   = g_sorted[i];
        const int snd = __ldg(&senders[e]);
        const float xv = g_x[(size_t)snd * 128 + f];
        const float4* ewp = (const float4*)(g_ew + (size_t)e * 16);
        const float4 e0 = ewp[0], e1 = ewp[1], e2 = ewp[2], e3 = ewp[3];
        acc[0]  = fmaf(e0.x, xv, acc[0]);  acc[1]  = fmaf(e0.y, xv, acc[1]);
        acc[2]  = fmaf(e0.z, xv, acc[2]);  acc[3]  = fmaf(e0.w, xv, acc[3]);
        acc[4]  = fmaf(e1.x, xv, acc[4]);  acc[5]  = fmaf(e1.y, xv, acc[5]);
        acc[6]  = fmaf(e1.z, xv, acc[6]);  acc[7]  = fmaf(e1.w, xv, acc[7]);
        acc[8]  = fmaf(e2.x, xv, acc[8]);  acc[9]  = fmaf(e2.y, xv, acc[9]);
        acc[10] = fmaf(e2.z, xv, acc[10]); acc[11] = fmaf(e2.w, xv, acc[11]);
        acc[12] = fmaf(e3.x, xv, acc[12]); acc[13] = fmaf(e3.y, xv, acc[13]);
        acc[14] = fmaf(e3.z, xv, acc[14]); acc[15] = fmaf(e3.w, xv, acc[15]);
    }

    float4* op = (float4*)(g_agg + (size_t)n * 2048 + f * 16);
    op[0] = make_float4(acc[0],  acc[1],  acc[2],  acc[3]);
    op[1] = make_float4(acc[4],  acc[5],  acc[6],  acc[7]);
    op[2] = make_float4(acc[8],  acc[9],  acc[10], acc[11]);
    op[3] = make_float4(acc[12], acc[13], acc[14], acc[15]);
}

// ---------------- launch ----------------
extern "C" void kernel_launch(void* const* d_in, const int* in_sizes, int n_in,
                              void* d_out, int out_size)
{
    const float* node_feats = (const float*)d_in[0];
    const float* edge_feats = (const float*)d_in[1];
    const float* radial     = (const float*)d_in[2];
    const int*   senders    = (const int*)d_in[3];
    const int*   receivers  = (const int*)d_in[4];
    const int*   mask       = (const int*)d_in[5];   // bool promoted to int32
    const float* W_up       = (const float*)d_in[6];
    const float* W_r1       = (const float*)d_in[7];
    const float* W_r2       = (const float*)d_in[8];
    const float* W_down     = (const float*)d_in[9];

    const int N = in_sizes[0] / FDIM;
    const int E = in_sizes[3];
    const int n4 = N * FDIM / 4;

    float* x_ptr;
    cudaGetSymbolAddress((void**)&x_ptr, g_x);

    dim3 ggrid((N + 127) / 128, 2);

    k_zero_counts<<<(N + 255) / 256, 256>>>(N);
    k_permute<<<(KDIM * FDIM * FDIM + 255) / 256, 256>>>(W_down);
    k_gemm<<<ggrid, 256>>>(node_feats, W_up, N, FDIM);
    k_combine<<<(n4 + 255) / 256, 256>>>(x_ptr, 1.0f, n4);
    k_radial<<<(E + 255) / 256, 256>>>(radial, edge_feats, mask, W_r1, W_r2, E);
    k_hist<<<(E + 255) / 256, 256>>>(receivers, E);
    k_scan<<<1, 1024>>>(N);
    k_scatter<<<(E + 255) / 256, 256>>>(receivers, E);
    k_agg<<<N, 128>>>(senders);
    float* agg_ptr;
    cudaGetSymbolAddress((void**)&agg_ptr, g_agg);
    float* wdp_ptr;
    cudaGetSymbolAddress((void**)&wdp_ptr, g_wdp);
    k_gemm<<<ggrid, 256>>>(agg_ptr, wdp_ptr, N, KDIM * FDIM);
    k_combine<<<(n4 + 255) / 256, 256>>>((float*)d_out, 0.1f, n4);
}

// round 17
// speedup vs baseline: 1.0034x; 1.0034x over previous
#include <cuda_runtime.h>
#include <cstdint>

#define NMAX 10000
#define EMAX 100000
#define FDIM 128
#define KDIM 16
#define RDIM 8
#define HDIM 64

// ---------------- scratch (static __device__ arrays; no allocation) ----------------
__device__ float g_x[NMAX * FDIM];                 // node_feats @ W_up        (5.1 MB)
__device__ float g_ew[EMAX * KDIM];                // masked weighted edge attrs (6.4 MB)
__device__ float g_agg[(size_t)NMAX * KDIM * FDIM];// aggregated messages, [n][f*16+k] (82 MB)
__device__ float g_wdp[KDIM * FDIM * FDIM];        // permuted W_down (1 MB)
__device__ float g_part[2][NMAX * FDIM];           // split-K partial sums (10.2 MB)
__device__ int   g_counts[NMAX];
__device__ int   g_offsets[NMAX + 1];
__device__ int   g_cursor[NMAX];
__device__ int   g_sorted[EMAX];

typedef unsigned long long ull;

// ---------------- f32x2 packed-FMA helpers (sm_103a) ----------------
__device__ __forceinline__ ull pack2(float x, float y) {
    ull r; asm("mov.b64 %0, {%1, %2};" : "=l"(r) : "f"(x), "f"(y)); return r;
}
__device__ __forceinline__ void unpack2(ull v, float& x, float& y) {
    asm("mov.b64 {%0, %1}, %2;" : "=f"(x), "=f"(y) : "l"(v));
}
__device__ __forceinline__ ull ffma2(ull a, ull b, ull c) {
    ull d; asm("fma.rn.f32x2 %0, %1, %2, %3;" : "=l"(d) : "l"(a), "l"(b), "l"(c)); return d;
}

// =====================================================================
// Split-K fp32 GEMM:  Cpart[split][M,128] = A[M, kbase:kbase+K/2] @ B[., 128]
// BM=128, BN=128, BK=16, 256 threads, gridDim.y = 2 splits.
// Microtile 8 rows x 8 cols (4 FFMA2 col-pairs). Double-buffered smem,
// single __syncthreads per k-tile.
// Thread (rt = tid>>4, ct = tid&15): rows rt*8..+7, col pairs {2ct,2ct+1}+32j.
// A reads: warp-broadcast (rt uniform in half-warp groups) - conflict-free.
// B reads: 16 consecutive ull per j - conflict-free.
// =====================================================================
__global__ void k_gemm(const float* __restrict__ A,
                       const float* __restrict__ B,
                       int M, int K)
{
    __shared__ ull As2[2][16][128];  // (a,a) duplicated pairs, 32 KB
    __shared__ ull Bs [2][16][64];   // column pairs,            16 KB

    const int tid = threadIdx.x;
    const int rt  = tid >> 4;              // 0..15 row tile
    const int ct  = tid & 15;              // 0..15 col tile
    const int m0  = blockIdx.x * 128;
    const int Ksplit = K >> 1;
    const int kbase  = blockIdx.y * Ksplit;
    float* __restrict__ Cp = &g_part[blockIdx.y][0];

    const int ntiles = Ksplit >> 4;

    // fill mappings (2 float4 per thread for each of A and B)
    const int qa0 = tid, qa1 = tid + 256;          // A float4 ids 0..511
    const int ar0 = qa0 >> 2, ak0 = (qa0 & 3) << 2;
    const int ar1 = qa1 >> 2, ak1 = (qa1 & 3) << 2;
    const int br0 = qa0 >> 5, bc0 = (qa0 & 31) << 2;
    const int br1 = qa1 >> 5, bc1 = (qa1 & 31) << 2;

    ull acc[8][4];
#pragma unroll
    for (int i = 0; i < 8; i++)
#pragma unroll
        for (int j = 0; j < 4; j++) acc[i][j] = 0ull;

    float4 pa0, pa1, pb0, pb1;

    // prefetch tile 0
    {
        const int kb = kbase;
        pa0 = (m0 + ar0 < M) ? *(const float4*)(A + (size_t)(m0 + ar0) * K + kb + ak0)
                             : make_float4(0.f, 0.f, 0.f, 0.f);
        pa1 = (m0 + ar1 < M) ? *(const float4*)(A + (size_t)(m0 + ar1) * K + kb + ak1)
                             : make_float4(0.f, 0.f, 0.f, 0.f);
        pb0 = *(const float4*)(B + (size_t)(kb + br0) * 128 + bc0);
        pb1 = *(const float4*)(B + (size_t)(kb + br1) * 128 + bc1);
    }
    // store tile 0 into buffer 0
    {
        As2[0][ak0 + 0][ar0] = pack2(pa0.x, pa0.x);
        As2[0][ak0 + 1][ar0] = pack2(pa0.y, pa0.y);
        As2[0][ak0 + 2][ar0] = pack2(pa0.z, pa0.z);
        As2[0][ak0 + 3][ar0] = pack2(pa0.w, pa0.w);
        As2[0][ak1 + 0][ar1] = pack2(pa1.x, pa1.x);
        As2[0][ak1 + 1][ar1] = pack2(pa1.y, pa1.y);
        As2[0][ak1 + 2][ar1] = pack2(pa1.z, pa1.z);
        As2[0][ak1 + 3][ar1] = pack2(pa1.w, pa1.w);
        const int c20 = bc0 >> 1, c21 = bc1 >> 1;
        Bs[0][br0][c20]     = pack2(pb0.x, pb0.y);
        Bs[0][br0][c20 + 1] = pack2(pb0.z, pb0.w);
        Bs[0][br1][c21]     = pack2(pb1.x, pb1.y);
        Bs[0][br1][c21 + 1] = pack2(pb1.z, pb1.w);
    }
    __syncthreads();

    const int rbase = rt * 8;

    for (int kt = 0; kt < ntiles; ++kt) {
        const int cur = kt & 1;
        const bool more = (kt + 1 < ntiles);

        if (more) {   // issue global prefetch early
            const int kb = kbase + (kt + 1) * 16;
            pa0 = (m0 + ar0 < M) ? *(const float4*)(A + (size_t)(m0 + ar0) * K + kb + ak0)
                                 : make_float4(0.f, 0.f, 0.f, 0.f);
            pa1 = (m0 + ar1 < M) ? *(const float4*)(A + (size_t)(m0 + ar1) * K + kb + ak1)
                                 : make_float4(0.f, 0.f, 0.f, 0.f);
            pb0 = *(const float4*)(B + (size_t)(kb + br0) * 128 + bc0);
            pb1 = *(const float4*)(B + (size_t)(kb + br1) * 128 + bc1);
        }

#pragma unroll
        for (int k = 0; k < 16; ++k) {
            ull a[8], b[4];
#pragma unroll
            for (int i = 0; i < 8; i++) a[i] = As2[cur][k][rbase + i];
#pragma unroll
            for (int j = 0; j < 4; j++) b[j] = Bs[cur][k][ct + 16 * j];
#pragma unroll
            for (int i = 0; i < 8; i++) {
#pragma unroll
                for (int j = 0; j < 4; j++)
                    acc[i][j] = ffma2(a[i], b[j], acc[i][j]);
            }
        }

        if (more) {
            const int nxt = cur ^ 1;
            As2[nxt][ak0 + 0][ar0] = pack2(pa0.x, pa0.x);
            As2[nxt][ak0 + 1][ar0] = pack2(pa0.y, pa0.y);
            As2[nxt][ak0 + 2][ar0] = pack2(pa0.z, pa0.z);
            As2[nxt][ak0 + 3][ar0] = pack2(pa0.w, pa0.w);
            As2[nxt][ak1 + 0][ar1] = pack2(pa1.x, pa1.x);
            As2[nxt][ak1 + 1][ar1] = pack2(pa1.y, pa1.y);
            As2[nxt][ak1 + 2][ar1] = pack2(pa1.z, pa1.z);
            As2[nxt][ak1 + 3][ar1] = pack2(pa1.w, pa1.w);
            const int c20 = bc0 >> 1, c21 = bc1 >> 1;
            Bs[nxt][br0][c20]     = pack2(pb0.x, pb0.y);
            Bs[nxt][br0][c20 + 1] = pack2(pb0.z, pb0.w);
            Bs[nxt][br1][c21]     = pack2(pb1.x, pb1.y);
            Bs[nxt][br1][c21 + 1] = pack2(pb1.z, pb1.w);
            __syncthreads();
        }
    }

#pragma unroll
    for (int i = 0; i < 8; i++) {
        const int row = m0 + rbase + i;
        if (row < M) {
#pragma unroll
            for (int j = 0; j < 4; j++) {
                float lo, hi; unpack2(acc[i][j], lo, hi);
                *(float2*)(Cp + (size_t)row * 128 + 2 * ct + 32 * j) =
                    make_float2(lo, hi);
            }
        }
    }
}

// combine split-K partials: dst = scale * (p0 + p1), float4 vectorized
__global__ void k_combine(float* __restrict__ dst, float scale, int n4) {
    const int i = blockIdx.x * 256 + threadIdx.x;
    if (i >= n4) return;
    const float4 a = ((const float4*)&g_part[0][0])[i];
    const float4 b = ((const float4*)&g_part[1][0])[i];
    ((float4*)dst)[i] = make_float4(scale * (a.x + b.x), scale * (a.y + b.y),
                                    scale * (a.z + b.z), scale * (a.w + b.w));
}

// ---------------- W_down permutation: row k*128+f  ->  row f*16+k ----------------
__global__ void k_permute(const float* __restrict__ Wd) {
    const int idx = blockIdx.x * 256 + threadIdx.x;
    if (idx >= KDIM * FDIM * FDIM) return;
    const int col = idx & 127;
    const int row = idx >> 7;       // 0..2047 = k*128+f
    const int k   = row >> 7;
    const int f   = row & 127;
    g_wdp[((f << 4) + k) * 128 + col] = Wd[idx];
}

// ---------------- radial MLP + masked edge weighting -> g_ew ----------------
// edge_mask arrives as int32 (harness promotes bool -> int32).
__global__ void k_radial(const float* __restrict__ radial,
                         const float* __restrict__ ef,
                         const int* __restrict__ mask,
                         const float* __restrict__ W1,
                         const float* __restrict__ W2,
                         int E)
{
    __shared__ float W1t[HDIM * RDIM];        // transposed: [j][i], 2 KB
    __shared__ ull   W2p[HDIM * KDIM / 2];    // row pairs:  [j][kp], 4 KB
    const int tid = threadIdx.x;
    for (int idx = tid; idx < HDIM * RDIM; idx += 256) {
        const int j = idx >> 3, i = idx & 7;
        W1t[idx] = W1[i * HDIM + j];
    }
    for (int idx = tid; idx < HDIM * KDIM / 2; idx += 256)
        W2p[idx] = pack2(W2[2 * idx], W2[2 * idx + 1]);
    __syncthreads();

    const int e = blockIdx.x * 256 + tid;
    if (e >= E) return;

    const float4 r0 = *(const float4*)(radial + (size_t)e * 8);
    const float4 r1 = *(const float4*)(radial + (size_t)e * 8 + 4);

    ull w[8];
#pragma unroll
    for (int kp = 0; kp < 8; kp++) w[kp] = 0ull;

#pragma unroll 4
    for (int j = 0; j < HDIM; j++) {
        const float4 c0 = *(const float4*)&W1t[j * 8];
        const float4 c1 = *(const float4*)&W1t[j * 8 + 4];
        float h = r0.x * c0.x;
        h = fmaf(r0.y, c0.y, h); h = fmaf(r0.z, c0.z, h); h = fmaf(r0.w, c0.w, h);
        h = fmaf(r1.x, c1.x, h); h = fmaf(r1.y, c1.y, h);
        h = fmaf(r1.z, c1.z, h); h = fmaf(r1.w, c1.w, h);
        const float s = __fdividef(h, 1.0f + __expf(-h));   // silu
        const ull ss = pack2(s, s);
        const ulonglong2* wp = (const ulonglong2*)&W2p[j * 8];
#pragma unroll
        for (int q = 0; q < 4; q++) {
            const ulonglong2 t = wp[q];
            w[2 * q]     = ffma2(ss, t.x, w[2 * q]);
            w[2 * q + 1] = ffma2(ss, t.y, w[2 * q + 1]);
        }
    }

    float wk[16];
#pragma unroll
    for (int kp = 0; kp < 8; kp++) unpack2(w[kp], wk[2 * kp], wk[2 * kp + 1]);

    const float m = (mask[e] != 0) ? 1.0f : 0.0f;
    const float4* efp = (const float4*)(ef + (size_t)e * 16);
    float4* op = (float4*)(g_ew + (size_t)e * 16);
#pragma unroll
    for (int q = 0; q < 4; q++) {
        const float4 v = efp[q];
        op[q] = make_float4(m * v.x * wk[q * 4 + 0], m * v.y * wk[q * 4 + 1],
                            m * v.z * wk[q * 4 + 2], m * v.w * wk[q * 4 + 3]);
    }
}

// ---------------- counting sort of edges by receiver ----------------
__global__ void k_zero_counts(int n) {
    const int i = blockIdx.x * 256 + threadIdx.x;
    if (i < n) g_counts[i] = 0;
}
__global__ void k_hist(const int* __restrict__ recv, int E) {
    const int e = blockIdx.x * 256 + threadIdx.x;
    if (e < E) atomicAdd(&g_counts[recv[e]], 1);
}
__global__ void k_scan(int n) {
    __shared__ int wsum[32];
    const int tid  = threadIdx.x;
    const int lane = tid & 31;
    const int wid  = tid >> 5;
    int carry = 0;
    for (int base = 0; base < n; base += 1024) {
        const int i = base + tid;
        const int v = (i < n) ? g_counts[i] : 0;
        int x = v;
#pragma unroll
        for (int off = 1; off < 32; off <<= 1) {
            const int y = __shfl_up_sync(0xffffffffu, x, off);
            if (lane >= off) x += y;
        }
        if (lane == 31) wsum[wid] = x;
        __syncthreads();
        if (wid == 0) {
            int s = wsum[lane];
#pragma unroll
            for (int off = 1; off < 32; off <<= 1) {
                const int y = __shfl_up_sync(0xffffffffu, s, off);
                if (lane >= off) s += y;
            }
            wsum[lane] = s;
        }
        __syncthreads();
        const int wbase = (wid > 0) ? wsum[wid - 1] : 0;
        const int excl  = carry + wbase + x - v;
        if (i < n) { g_offsets[i] = excl; g_cursor[i] = excl; }
        carry += wsum[31];
        __syncthreads();
    }
    if (tid == 0) g_offsets[n] = carry;
}
__global__ void k_scatter(const int* __restrict__ recv, int E) {
    const int e = blockIdx.x * 256 + threadIdx.x;
    if (e < E) {
        const int p = atomicAdd(&g_cursor[recv[e]], 1);
        g_sorted[p] = e;
    }
}

// ---------------- per-receiver aggregation -> g_agg [n][f*16+k] ----------------
__global__ void k_agg(const int* __restrict__ senders) {
    const int n = blockIdx.x;
    const int f = threadIdx.x;     // 128 threads, one output channel each
    const int s0 = g_offsets[n];
    const int s1 = g_offsets[n + 1];
    float acc[16];
#pragma unroll
    for (int k = 0; k < 16; k++) acc[k] = 0.f;

    for (int i = s0; i < s1; ++i) {
        const int e   = g_sorted[i];
        const int snd = __ldg(&senders[e]);
        const float xv = g_x[(size_t)snd * 128 + f];
        const float4* ewp = (const float4*)(g_ew + (size_t)e * 16);
        const float4 e0 = ewp[0], e1 = ewp[1], e2 = ewp[2], e3 = ewp[3];
        acc[0]  = fmaf(e0.x, xv, acc[0]);  acc[1]  = fmaf(e0.y, xv, acc[1]);
        acc[2]  = fmaf(e0.z, xv, acc[2]);  acc[3]  = fmaf(e0.w, xv, acc[3]);
        acc[4]  = fmaf(e1.x, xv, acc[4]);  acc[5]  = fmaf(e1.y, xv, acc[5]);
        acc[6]  = fmaf(e1.z, xv, acc[6]);  acc[7]  = fmaf(e1.w, xv, acc[7]);
        acc[8]  = fmaf(e2.x, xv, acc[8]);  acc[9]  = fmaf(e2.y, xv, acc[9]);
        acc[10] = fmaf(e2.z, xv, acc[10]); acc[11] = fmaf(e2.w, xv, acc[11]);
        acc[12] = fmaf(e3.x, xv, acc[12]); acc[13] = fmaf(e3.y, xv, acc[13]);
        acc[14] = fmaf(e3.z, xv, acc[14]); acc[15] = fmaf(e3.w, xv, acc[15]);
    }

    float4* op = (float4*)(g_agg + (size_t)n * 2048 + f * 16);
    op[0] = make_float4(acc[0],  acc[1],  acc[2],  acc[3]);
    op[1] = make_float4(acc[4],  acc[5],  acc[6],  acc[7]);
    op[2] = make_float4(acc[8],  acc[9],  acc[10], acc[11]);
    op[3] = make_float4(acc[12], acc[13], acc[14], acc[15]);
}

// ---------------- launch ----------------
extern "C" void kernel_launch(void* const* d_in, const int* in_sizes, int n_in,
                              void* d_out, int out_size)
{
    const float* node_feats = (const float*)d_in[0];
    const float* edge_feats = (const float*)d_in[1];
    const float* radial     = (const float*)d_in[2];
    const int*   senders    = (const int*)d_in[3];
    const int*   receivers  = (const int*)d_in[4];
    const int*   mask       = (const int*)d_in[5];   // bool promoted to int32
    const float* W_up       = (const float*)d_in[6];
    const float* W_r1       = (const float*)d_in[7];
    const float* W_r2       = (const float*)d_in[8];
    const float* W_down     = (const float*)d_in[9];

    const int N = in_sizes[0] / FDIM;
    const int E = in_sizes[3];
    const int n4 = N * FDIM / 4;

    float* x_ptr;
    cudaGetSymbolAddress((void**)&x_ptr, g_x);

    dim3 ggrid((N + 127) / 128, 2);

    k_zero_counts<<<(N + 255) / 256, 256>>>(N);
    k_permute<<<(KDIM * FDIM * FDIM + 255) / 256, 256>>>(W_down);
    k_gemm<<<ggrid, 256>>>(node_feats, W_up, N, FDIM);
    k_combine<<<(n4 + 255) / 256, 256>>>(x_ptr, 1.0f, n4);
    k_radial<<<(E + 255) / 256, 256>>>(radial, edge_feats, mask, W_r1, W_r2, E);
    k_hist<<<(E + 255) / 256, 256>>>(receivers, E);
    k_scan<<<1, 1024>>>(N);
    k_scatter<<<(E + 255) / 256, 256>>>(receivers, E);
    k_agg<<<N, 128>>>(senders);
    float* agg_ptr;
    cudaGetSymbolAddress((void**)&agg_ptr, g_agg);
    float* wdp_ptr;
    cudaGetSymbolAddress((void**)&wdp_ptr, g_wdp);
    k_gemm<<<ggrid, 256>>>(agg_ptr, wdp_ptr, N, KDIM * FDIM);
    k_combine<<<(n4 + 255) / 256, 256>>>((float*)d_out, 0.1f, n4);
}